// round 13
// baseline (speedup 1.0000x reference)
#include <cuda_runtime.h>
#include <math.h>
#include <stdint.h>

// Problem dims
#define BB 4
#define MM 2048
#define NN 2048
#define DD 256
#define D2 512
#define RALLC 8192
#define LN_EPS 1e-5f
#define TH_VAL 0.1f
#define NEG_HUGE -3.0e38f

// ---------------- scratch ----------------
#define SZP (4LL*2048*2048)
#define SZV (4LL*2048*256)
#define SZH (4LL*2048*512)
#define SZS (8192LL)
#define SZPART (65536LL)
#define STATN (4*16*2048)

constexpr size_t O_E   = 0;                 // exp(adj), also serves as P01 source
constexpr size_t O_SIM = O_E + SZP;
constexpr size_t O_V0  = O_SIM + SZP;
constexpr size_t O_V1  = O_V0 + SZV;
constexpr size_t O_MP0 = O_V1 + SZV;
constexpr size_t O_MP1 = O_MP0 + SZV;
constexpr size_t O_H0  = O_MP1 + SZV;
constexpr size_t O_H1  = O_H0 + SZH;
constexpr size_t O_D0  = O_H1 + SZH;
constexpr size_t O_D1  = O_D0 + SZV;
constexpr size_t O_MD0 = O_D1 + SZV;
constexpr size_t O_MD1 = O_MD0 + SZV;
constexpr size_t O_RINV = O_MD1 + SZV;
constexpr size_t O_CINV = O_RINV + SZS;
constexpr size_t O_RLSE = O_CINV + SZS;
constexpr size_t O_CLSE = O_RLSE + SZS;
constexpr size_t O_Z0   = O_CLSE + SZS;
constexpr size_t O_Z1   = O_Z0 + SZS;
constexpr size_t O_RADJ = O_Z1 + SZS;
constexpr size_t O_CADJ = O_RADJ + SZS;
constexpr size_t O_BRD0 = O_CADJ + SZS;
constexpr size_t O_BRD1 = O_BRD0 + SZS;
constexpr size_t O_ROWV = O_BRD1 + SZS;
constexpr size_t O_MS0  = O_ROWV + SZS;
constexpr size_t O_PM   = O_MS0 + SZS;
constexpr size_t O_PAV  = O_PM + SZPART;
constexpr size_t O_WCAT = O_PAV + SZPART;          // 512*512
constexpr size_t O_BCAT = O_WCAT + 262144;         // 512
constexpr size_t O_RP   = O_BCAT + 512;            // STATN
constexpr size_t O_CP   = O_RP + STATN;            // STATN
constexpr size_t O_TOTAL = O_CP + STATN;

__device__ __align__(16) float g_scratch[O_TOTAL];
__device__ int g_iscratch[3 * 8192 + 65536];

__device__ __forceinline__ float softplusf(float x) {
    return fmaxf(x, 0.f) + log1pf(expf(-fabsf(x)));
}

// ================= tf32x3 MMA GEMM (mask-split), double-buffered =================
__device__ __forceinline__ float lo_part(float x) {
    float h = __uint_as_float(__float_as_uint(x) & 0xFFFFE000u);
    return x - h;
}

__device__ __forceinline__ void mma8(float* c, const uint32_t* a, const uint32_t* b) {
    asm volatile(
        "mma.sync.aligned.m16n8k8.row.col.f32.tf32.tf32.f32 "
        "{%0,%1,%2,%3}, {%4,%5,%6,%7}, {%8,%9}, {%0,%1,%2,%3};\n"
        : "+f"(c[0]), "+f"(c[1]), "+f"(c[2]), "+f"(c[3])
        : "r"(a[0]), "r"(a[1]), "r"(a[2]), "r"(a[3]), "r"(b[0]), "r"(b[1]));
}

#define BMT 128
#define ASTR (BMT + 4)

// TRANSA: when hb==1 the A tile is read as E^T (16xK rows of E, transposed in smem store)
// SPLITA: A columns k<kSplit from Ap (x side), k>=kSplit from Aaltp (mp side)
template <int BN, bool B_IS_NK, bool STATS, bool TRANSA, bool SPLITA>
__global__ __launch_bounds__(256, 2) void mma_gemm(
    const float* __restrict__ A, const float* __restrict__ A2,
    const float* __restrict__ Bg, const float* __restrict__ Bg2,
    const float* __restrict__ bias,
    const float* __restrict__ res, const float* __restrict__ res2,
    float scale, float* __restrict__ C,
    int N, int K, int subbatch,
    long sA, long sB, long sC, long sRes,
    float* __restrict__ rp, float* __restrict__ cp,
    const float* __restrict__ rs, const float* __restrict__ rs2,
    long ldat,
    const float* __restrict__ Aalt, long sAalt, int kSplit)
{
    constexpr int WN = BN / 32;
    constexpr int WM = 8 / WN;
    constexpr int MROWS = BMT / WM;
    constexpr int MFRAG = MROWS / 16;
    constexpr int NFRAG = 4;
    constexpr int BSTR = BN + 4;
    constexpr int BQ = (BN * 16 / 4) / 256;

    extern __shared__ float2 dynsm[];
    float2* AsBuf = dynsm;
    float2* BsBuf = dynsm + 2 * 16 * ASTR;

    int b = blockIdx.z;
    int hb = (subbatch > 0 && b >= subbatch) ? 1 : 0;
    int b2 = b - hb * subbatch;
    const float* Ap = A2 ? ((hb ? A2 : A) + (long)b2 * sA) : (A + (long)b * sA);
    const float* Bp = Bg2 ? ((hb ? Bg2 : Bg) + (long)b2 * sB) : (Bg + (long)b * sB);
    const float* Rp = res ? (res2 ? ((hb ? res2 : res) + (long)b2 * sRes)
                                  : (res + (long)b * sRes)) : (const float*)0;
    const float* Aaltp = SPLITA ? (Aalt + (long)hb * sAalt) : (const float*)0;
    const float* rsp = rs ? ((hb ? rs2 : rs) + (long)b2 * 2048) : (const float*)0;
    float* Cp = C + (long)b * sC;
    bool atrans = TRANSA && hb;

    int bm = blockIdx.y * BMT;
    int bn = blockIdx.x * BN;
    int tid = threadIdx.x;
    int wid = tid >> 5, lane = tid & 31;
    int g = lane >> 2, t4 = lane & 3;
    int wn = wid % WN, wm = wid / WN;
    int m0 = wm * MROWS;

    float acc[MFRAG][NFRAG][4];
    #pragma unroll
    for (int i = 0; i < MFRAG; i++)
        #pragma unroll
        for (int j = 0; j < NFRAG; j++)
            #pragma unroll
            for (int q = 0; q < 4; q++) acc[i][j][q] = 0.f;

    float4 pa[2];
    float4 pb[BQ];

    int a_row = tid & 127;
    int a_kh = (tid >> 7) * 4;
    // trans-path indices
    int at_k = tid >> 5;            // base k row 0..7 (two q give 0..15)
    int at_m4 = (tid & 31) * 4;

#define LOAD_A(k0_) do { \
    if (atrans) { \
        _Pragma("unroll") \
        for (int q = 0; q < 2; q++) { \
            int kk = at_k + q * 8; \
            pa[q] = *(const float4*)(Ap + (long)((k0_) + kk) * ldat + bm + at_m4); \
        } \
    } else if (SPLITA) { \
        bool second = ((k0_) >= kSplit); \
        const float* base = second ? Aaltp : Ap; \
        int kloc = second ? (k0_) - kSplit : (k0_); \
        _Pragma("unroll") \
        for (int q = 0; q < 2; q++) \
            pa[q] = *(const float4*)(base + (long)(bm + a_row) * kSplit + kloc + q * 8 + a_kh); \
    } else { \
        _Pragma("unroll") \
        for (int q = 0; q < 2; q++) \
            pa[q] = *(const float4*)(Ap + (long)(bm + a_row) * K + (k0_) + q * 8 + a_kh); \
    } \
} while (0)

#define STORE_A(st_) do { \
    if (atrans) { \
        _Pragma("unroll") \
        for (int q = 0; q < 2; q++) { \
            int kk = at_k + q * 8; \
            float2* dst = &AsBuf[((st_) * 16 + kk) * ASTR + at_m4]; \
            dst[0] = make_float2(pa[q].x, lo_part(pa[q].x)); \
            dst[1] = make_float2(pa[q].y, lo_part(pa[q].y)); \
            dst[2] = make_float2(pa[q].z, lo_part(pa[q].z)); \
            dst[3] = make_float2(pa[q].w, lo_part(pa[q].w)); \
        } \
    } else { \
        _Pragma("unroll") \
        for (int q = 0; q < 2; q++) { \
            int k4 = q * 8 + a_kh; \
            AsBuf[((st_) * 16 + k4 + 0) * ASTR + a_row] = make_float2(pa[q].x, lo_part(pa[q].x)); \
            AsBuf[((st_) * 16 + k4 + 1) * ASTR + a_row] = make_float2(pa[q].y, lo_part(pa[q].y)); \
            AsBuf[((st_) * 16 + k4 + 2) * ASTR + a_row] = make_float2(pa[q].z, lo_part(pa[q].z)); \
            AsBuf[((st_) * 16 + k4 + 3) * ASTR + a_row] = make_float2(pa[q].w, lo_part(pa[q].w)); \
        } \
    } \
} while (0)

#define LOAD_B(k0_) do { \
    _Pragma("unroll") \
    for (int q = 0; q < BQ; q++) { \
        int idx = q * 256 + tid; \
        if (B_IS_NK) { \
            int row = idx % BN, k4 = (idx / BN) * 4; \
            pb[q] = *(const float4*)(Bp + (long)(bn + row) * K + (k0_) + k4); \
        } else { \
            int k = idx / (BN / 4), n4 = (idx % (BN / 4)) * 4; \
            pb[q] = *(const float4*)(Bp + (long)((k0_) + k) * N + bn + n4); \
        } \
    } \
} while (0)

#define STORE_B(st_) do { \
    _Pragma("unroll") \
    for (int q = 0; q < BQ; q++) { \
        int idx = q * 256 + tid; \
        if (B_IS_NK) { \
            int row = idx % BN, k4 = (idx / BN) * 4; \
            BsBuf[((st_) * 16 + k4 + 0) * BSTR + row] = make_float2(pb[q].x, lo_part(pb[q].x)); \
            BsBuf[((st_) * 16 + k4 + 1) * BSTR + row] = make_float2(pb[q].y, lo_part(pb[q].y)); \
            BsBuf[((st_) * 16 + k4 + 2) * BSTR + row] = make_float2(pb[q].z, lo_part(pb[q].z)); \
            BsBuf[((st_) * 16 + k4 + 3) * BSTR + row] = make_float2(pb[q].w, lo_part(pb[q].w)); \
        } else { \
            int k = idx / (BN / 4), n4 = (idx % (BN / 4)) * 4; \
            BsBuf[((st_) * 16 + k) * BSTR + n4 + 0] = make_float2(pb[q].x, lo_part(pb[q].x)); \
            BsBuf[((st_) * 16 + k) * BSTR + n4 + 1] = make_float2(pb[q].y, lo_part(pb[q].y)); \
            BsBuf[((st_) * 16 + k) * BSTR + n4 + 2] = make_float2(pb[q].z, lo_part(pb[q].z)); \
            BsBuf[((st_) * 16 + k) * BSTR + n4 + 3] = make_float2(pb[q].w, lo_part(pb[q].w)); \
        } \
    } \
} while (0)

#define COMPUTE(st_) do { \
    _Pragma("unroll") \
    for (int kk = 0; kk < 16; kk += 8) { \
        int kA = kk + t4; \
        uint32_t bh[NFRAG][2], bl[NFRAG][2]; \
        _Pragma("unroll") \
        for (int fn = 0; fn < NFRAG; fn++) { \
            int n = wn * 32 + fn * 8 + g; \
            float2 f0 = BsBuf[((st_) * 16 + kA) * BSTR + n]; \
            float2 f1 = BsBuf[((st_) * 16 + kA + 4) * BSTR + n]; \
            bh[fn][0] = __float_as_uint(f0.x); bh[fn][1] = __float_as_uint(f1.x); \
            bl[fn][0] = __float_as_uint(f0.y); bl[fn][1] = __float_as_uint(f1.y); \
        } \
        _Pragma("unroll") \
        for (int fm = 0; fm < MFRAG; fm++) { \
            int m = m0 + fm * 16 + g; \
            float2 f0 = AsBuf[((st_) * 16 + kA) * ASTR + m]; \
            float2 f1 = AsBuf[((st_) * 16 + kA) * ASTR + m + 8]; \
            float2 f2 = AsBuf[((st_) * 16 + kA + 4) * ASTR + m]; \
            float2 f3 = AsBuf[((st_) * 16 + kA + 4) * ASTR + m + 8]; \
            uint32_t ah[4] = {__float_as_uint(f0.x), __float_as_uint(f1.x), \
                              __float_as_uint(f2.x), __float_as_uint(f3.x)}; \
            uint32_t al[4] = {__float_as_uint(f0.y), __float_as_uint(f1.y), \
                              __float_as_uint(f2.y), __float_as_uint(f3.y)}; \
            _Pragma("unroll") \
            for (int fn = 0; fn < NFRAG; fn++) { \
                mma8(acc[fm][fn], ah, bh[fn]); \
                mma8(acc[fm][fn], ah, bl[fn]); \
                mma8(acc[fm][fn], al, bh[fn]); \
            } \
        } \
    } \
} while (0)

    int nt = K / 16;
    LOAD_A(0); LOAD_B(0);
    STORE_A(0); STORE_B(0);
    __syncthreads();
    for (int t = 0; t < nt; t++) {
        int st = t & 1;
        bool more = (t + 1 < nt);
        if (more) { LOAD_A((t + 1) * 16); LOAD_B((t + 1) * 16); }
        COMPUTE(st);
        if (more) { STORE_A(st ^ 1); STORE_B(st ^ 1); }
        __syncthreads();
    }

    if (STATS) {
        float* sst = (float*)dynsm;
        float eacc[MFRAG][NFRAG][4];
        #pragma unroll
        for (int fm = 0; fm < MFRAG; fm++)
            #pragma unroll
            for (int fn = 0; fn < NFRAG; fn++)
                #pragma unroll
                for (int q = 0; q < 4; q++)
                    eacc[fm][fn][q] = expf(acc[fm][fn][q]);
        #pragma unroll
        for (int fm = 0; fm < MFRAG; fm++) {
            #pragma unroll
            for (int off = 0; off < 2; off++) {
                float s = 0.f;
                #pragma unroll
                for (int fn = 0; fn < NFRAG; fn++)
                    s += eacc[fm][fn][off * 2] + eacc[fm][fn][off * 2 + 1];
                s += __shfl_xor_sync(0xffffffffu, s, 1);
                s += __shfl_xor_sync(0xffffffffu, s, 2);
                if (t4 == 0) {
                    int lr = m0 + fm * 16 + off * 8 + g;
                    sst[wn * 128 + lr] = s;
                }
            }
        }
        #pragma unroll
        for (int fn = 0; fn < NFRAG; fn++) {
            #pragma unroll
            for (int c2 = 0; c2 < 2; c2++) {
                float s = 0.f;
                #pragma unroll
                for (int fm = 0; fm < MFRAG; fm++)
                    s += eacc[fm][fn][c2] + eacc[fm][fn][2 + c2];
                s += __shfl_xor_sync(0xffffffffu, s, 4);
                s += __shfl_xor_sync(0xffffffffu, s, 8);
                s += __shfl_xor_sync(0xffffffffu, s, 16);
                if (g == 0) {
                    int lc = wn * 32 + fn * 8 + t4 * 2 + c2;
                    sst[512 + wm * 128 + lc] = s;
                }
            }
        }
        __syncthreads();
        if (tid < 128) {
            float s = sst[tid];
            #pragma unroll
            for (int w = 1; w < WN; w++) s += sst[w * 128 + tid];
            long ro = ((long)blockIdx.z * 16 + blockIdx.x) * 2048 + bm + tid;
            rp[ro] = s;
            float sc = sst[512 + tid];
            #pragma unroll
            for (int w = 1; w < WM; w++) sc += sst[512 + w * 128 + tid];
            long co = ((long)blockIdx.z * 16 + blockIdx.y) * 2048 + bn + tid;
            cp[co] = sc;
        }
        __syncthreads();
    }

    // epilogue store
    #pragma unroll
    for (int fm = 0; fm < MFRAG; fm++) {
        int row0 = bm + m0 + fm * 16 + g;
        float r0s = rsp ? rsp[row0] : 1.f;
        float r1s = rsp ? rsp[row0 + 8] : 1.f;
        #pragma unroll
        for (int fn = 0; fn < NFRAG; fn++) {
            int col0 = bn + wn * 32 + fn * 8 + t4 * 2;
            float b0 = bias ? bias[col0] : 0.f;
            float b1 = bias ? bias[col0 + 1] : 0.f;
            float v00 = (acc[fm][fn][0] + b0) * scale * r0s;
            float v01 = (acc[fm][fn][1] + b1) * scale * r0s;
            float v10 = (acc[fm][fn][2] + b0) * scale * r1s;
            float v11 = (acc[fm][fn][3] + b1) * scale * r1s;
            if (Rp) {
                v00 += Rp[(long)row0 * N + col0];
                v01 += Rp[(long)row0 * N + col0 + 1];
                v10 += Rp[(long)(row0 + 8) * N + col0];
                v11 += Rp[(long)(row0 + 8) * N + col0 + 1];
            }
            *(float2*)&Cp[(long)row0 * N + col0] = make_float2(v00, v01);
            *(float2*)&Cp[(long)(row0 + 8) * N + col0] = make_float2(v10, v11);
        }
    }
#undef LOAD_A
#undef STORE_A
#undef LOAD_B
#undef STORE_B
#undef COMPUTE
}

constexpr int SMEM_GEMM(int BN) {
    return (2 * 16 * (BMT + 4) + 2 * 16 * (BN + 4)) * (int)sizeof(float2);
}

// ================= weight folding =================
__global__ void fold_kernel(const float* __restrict__ Wf1, const float* __restrict__ Wo,
                            float* __restrict__ Wcat)
{
    int i = blockIdx.x;
    int k = threadIdx.x;
    float a0 = 0.f, a1 = 0.f, a2 = 0.f, a3 = 0.f;
    const float* wrow = Wf1 + (size_t)i * 512 + 256;
    #pragma unroll 4
    for (int j = 0; j < 256; j += 4) {
        a0 = fmaf(wrow[j + 0], Wo[(j + 0) * 256 + k], a0);
        a1 = fmaf(wrow[j + 1], Wo[(j + 1) * 256 + k], a1);
        a2 = fmaf(wrow[j + 2], Wo[(j + 2) * 256 + k], a2);
        a3 = fmaf(wrow[j + 3], Wo[(j + 3) * 256 + k], a3);
    }
    Wcat[(size_t)i * 512 + 256 + k] = (a0 + a1) + (a2 + a3);
    Wcat[(size_t)i * 512 + k] = Wf1[(size_t)i * 512 + k];
}

__global__ void bfold_kernel(const float* __restrict__ Wf1, const float* __restrict__ bo,
                             const float* __restrict__ bf1, float* __restrict__ bcat)
{
    int warp = (blockIdx.x * blockDim.x + threadIdx.x) >> 5;
    int lane = threadIdx.x & 31;
    if (warp >= 512) return;
    float s = 0.f;
    for (int j = lane; j < 256; j += 32)
        s += Wf1[(size_t)warp * 512 + 256 + j] * bo[j];
    for (int o = 16; o; o >>= 1) s += __shfl_down_sync(0xffffffffu, s, o);
    if (lane == 0) bcat[warp] = bf1[warp] + s;
}

// ================= adj softmax: E = exp(adj), row sums =================
__global__ void expstat_kernel(const float* __restrict__ adj, float* __restrict__ E,
                               float* __restrict__ rinv)
{
    int b = blockIdx.y, row = blockIdx.x, tid = threadIdx.x;
    const float4* ar = (const float4*)(adj + ((size_t)b * MM + row) * NN);
    float4* er = (float4*)(E + ((size_t)b * MM + row) * NN);
    float s = 0.f;
    #pragma unroll
    for (int it = 0; it < 2; it++) {
        int j = tid + it * 256;
        float4 v = ar[j];
        float4 e = make_float4(expf(v.x), expf(v.y), expf(v.z), expf(v.w));
        er[j] = e;
        s += (e.x + e.y) + (e.z + e.w);
    }
    __shared__ float red[256];
    red[tid] = s; __syncthreads();
    for (int o = 128; o; o >>= 1) { if (tid < o) red[tid] += red[tid + o]; __syncthreads(); }
    if (tid == 0) rinv[b * MM + row] = 1.f / red[0];
}

__global__ void colsum1_kernel(const float* __restrict__ E, float* __restrict__ ps)
{
    int b = blockIdx.z, ch = blockIdx.y;
    int col = blockIdx.x * 256 + threadIdx.x;
    const float* Eb = E + (size_t)b * MM * NN;
    int r0 = ch * 256;
    float s0 = 0.f, s1 = 0.f, s2 = 0.f, s3 = 0.f;
    for (int i = 0; i < 256; i += 4) {
        s0 += Eb[(size_t)(r0 + i + 0) * NN + col];
        s1 += Eb[(size_t)(r0 + i + 1) * NN + col];
        s2 += Eb[(size_t)(r0 + i + 2) * NN + col];
        s3 += Eb[(size_t)(r0 + i + 3) * NN + col];
    }
    ps[((size_t)b * 8 + ch) * NN + col] = (s0 + s1) + (s2 + s3);
}

__global__ void colsum2_kernel(const float* __restrict__ ps, float* __restrict__ cinv)
{
    int idx = blockIdx.x * blockDim.x + threadIdx.x;
    if (idx >= BB * NN) return;
    int b = idx / NN, col = idx % NN;
    size_t base = (size_t)b * 8 * NN + col;
    float s = 0.f;
    #pragma unroll
    for (int ch = 0; ch < 8; ch++) s += ps[base + (size_t)ch * NN];
    cinv[idx] = 1.f / s;
}

// ================= merge LSE partials =================
__global__ void merge_lse_kernel(const float* __restrict__ rp, const float* __restrict__ cp,
                                 float* __restrict__ rlse, float* __restrict__ clse)
{
    int idx = blockIdx.x * blockDim.x + threadIdx.x;
    if (idx >= 2 * 8192) return;
    bool iscol = idx >= 8192;
    int j = iscol ? idx - 8192 : idx;
    int b = j / 2048, r = j % 2048;
    const float* pm = iscol ? cp : rp;
    long base = ((long)b * 16) * 2048 + r;
    float s = 0.f;
    #pragma unroll
    for (int t = 0; t < 16; t++) s += pm[base + (long)t * 2048];
    float lse = logf(s);
    if (iscol) clse[j] = lse; else rlse[j] = lse;
}

// ================= col argmax =================
#define RCH 256
__global__ void colamax1_kernel(const float* __restrict__ sim, const float* __restrict__ radj,
                                float* __restrict__ pav, int* __restrict__ pai)
{
    int b = blockIdx.z, ch = blockIdx.y;
    int tid = threadIdx.x;
    int col = blockIdx.x * 32 + (tid & 31);
    int part = tid >> 5;
    const float* Sb = sim + (size_t)b * MM * NN;
    int r0 = ch * RCH;
    float bv[4]; int bx[4];
    #pragma unroll
    for (int q = 0; q < 4; q++) { bv[q] = NEG_HUGE; bx[q] = 0; }
    #pragma unroll 2
    for (int it = 0; it < 32; it += 4) {
        #pragma unroll
        for (int q = 0; q < 4; q++) {
            int i = r0 + part + (it + q) * 8;
            float v = 2.f * Sb[(size_t)i * NN + col] + radj[b * MM + i];
            if (v > bv[q]) { bv[q] = v; bx[q] = i; }
        }
    }
    float best = bv[0]; int bi = bx[0];
    #pragma unroll
    for (int q = 1; q < 4; q++)
        if (bv[q] > best || (bv[q] == best && bx[q] < bi)) { best = bv[q]; bi = bx[q]; }
    __shared__ float sv[256]; __shared__ int si[256];
    sv[tid] = best; si[tid] = bi; __syncthreads();
    if (part == 0) {
        for (int p = 1; p < 8; p++) {
            float v2 = sv[p * 32 + tid]; int i2 = si[p * 32 + tid];
            if (v2 > best || (v2 == best && i2 < bi)) { best = v2; bi = i2; }
        }
        size_t o = ((size_t)b * 8 + ch) * NN + col;
        pav[o] = best; pai[o] = bi;
    }
}

__global__ void colamax2_kernel(const float* __restrict__ pav, const int* __restrict__ pai,
                                int* __restrict__ colj)
{
    int idx = blockIdx.x * blockDim.x + threadIdx.x;
    if (idx >= BB * NN) return;
    int b = idx / NN, col = idx % NN;
    size_t base = (size_t)b * 8 * NN + col;
    float best = pav[base]; int bi = pai[base];
    for (int ch = 1; ch < 8; ch++) {
        float v2 = pav[base + (size_t)ch * NN];
        int i2 = pai[base + (size_t)ch * NN];
        if (v2 > best || (v2 == best && i2 < bi)) { best = v2; bi = i2; }
    }
    colj[idx] = bi;
}

// ---------------- layernorm + exact gelu ----------------
__global__ void ln_gelu_kernel(float* __restrict__ H, const float* __restrict__ g,
                               const float* __restrict__ bb)
{
    int row = blockIdx.x, tid = threadIdx.x;
    float* h = H + (size_t)row * 512;
    float x[4];
    float s = 0.f;
    __shared__ float red[128];
    #pragma unroll
    for (int i = 0; i < 4; i++) { x[i] = h[tid + i * 128]; s += x[i]; }
    red[tid] = s; __syncthreads();
    for (int o = 64; o; o >>= 1) { if (tid < o) red[tid] += red[tid + o]; __syncthreads(); }
    float mu = red[0] * (1.f / 512.f); __syncthreads();
    float s2 = 0.f;
    #pragma unroll
    for (int i = 0; i < 4; i++) { float d = x[i] - mu; s2 += d * d; }
    red[tid] = s2; __syncthreads();
    for (int o = 64; o; o >>= 1) { if (tid < o) red[tid] += red[tid + o]; __syncthreads(); }
    float rstd = rsqrtf(red[0] * (1.f / 512.f) + LN_EPS);
    #pragma unroll
    for (int i = 0; i < 4; i++) {
        int c = tid + i * 128;
        float y = (x[i] - mu) * rstd * g[c] + bb[c];
        h[c] = y * 0.5f * (1.f + erff(y * 0.70710678118654752f));
    }
}

// ---------------- z = d @ Wz + bz ----------------
__global__ void zdot_kernel(const float* __restrict__ Dm, const float* __restrict__ Wz,
                            const float* __restrict__ bz, float* __restrict__ z, int rows)
{
    int warp = (blockIdx.x * blockDim.x + threadIdx.x) >> 5;
    int lane = threadIdx.x & 31;
    if (warp >= rows) return;
    const float* r = Dm + (size_t)warp * DD;
    float s = 0.f;
    for (int k = lane; k < DD; k += 32) s += r[k] * Wz[k];
    for (int o = 16; o; o >>= 1) s += __shfl_down_sync(0xffffffffu, s, o);
    if (lane == 0) z[warp] = s + bz[0];
}

// ---------------- prep ----------------
__global__ void prep_kernel(const float* __restrict__ z0, const float* __restrict__ z1,
                            const float* __restrict__ rlse, const float* __restrict__ clse,
                            float* __restrict__ radj, float* __restrict__ cadj,
                            float* __restrict__ brd0, float* __restrict__ brd1)
{
    int idx = blockIdx.x * blockDim.x + threadIdx.x;
    if (idx >= 8192) return;
    float a = z0[idx], b = z1[idx];
    radj[idx] = -softplusf(-a) - rlse[idx];
    cadj[idx] = -softplusf(-b) - clse[idx];
    brd0[idx] = -softplusf(a);
    brd1[idx] = -softplusf(b);
}

// ---------------- scores assembly + fused row argmax ----------------
__global__ void assemble_kernel(const float* __restrict__ sim,
                                const float* __restrict__ radj, const float* __restrict__ cadj,
                                const float* __restrict__ brd0, const float* __restrict__ brd1,
                                float* __restrict__ out,
                                float* __restrict__ rowv, int* __restrict__ rowj)
{
    int b = blockIdx.y, i = blockIdx.x, tid = threadIdx.x;
    float* o = out + (size_t)b * 2049 * 2049 + (size_t)i * 2049;
    if (i < MM) {
        const float* sr = sim + (size_t)b * MM * NN + (size_t)i * NN;
        float ra = radj[b * MM + i];
        float best = NEG_HUGE; int bj = 0;
        for (int j = tid; j < NN; j += 256) {
            float v = 2.f * sr[j] + cadj[b * NN + j];
            o[j] = v + ra;
            if (v > best) { best = v; bj = j; }
        }
        __shared__ float sv[256]; __shared__ int sj[256];
        sv[tid] = best; sj[tid] = bj; __syncthreads();
        for (int off = 128; off; off >>= 1) {
            if (tid < off) {
                float v2 = sv[tid + off]; int j2 = sj[tid + off];
                if (v2 > sv[tid] || (v2 == sv[tid] && j2 < sj[tid])) { sv[tid] = v2; sj[tid] = j2; }
            }
            __syncthreads();
        }
        if (tid == 0) {
            o[NN] = brd0[b * MM + i];
            rowv[b * MM + i] = sv[0] + ra;
            rowj[b * MM + i] = sj[0];
        }
    } else {
        for (int j = tid; j < NN; j += 256)
            o[j] = brd1[b * NN + j];
        if (tid == 0) o[NN] = 0.f;
    }
}

// ---------------- mutual-match filter ----------------
__global__ void filter0_kernel(const int* __restrict__ rowj, const int* __restrict__ colj,
                               const float* __restrict__ rowv,
                               float* __restrict__ ms0_s, int* __restrict__ valid0,
                               float* __restrict__ out_m0, float* __restrict__ out_ms0)
{
    int idx = blockIdx.x * blockDim.x + threadIdx.x;
    if (idx >= 8192) return;
    int b = idx / MM, i = idx % MM;
    int i0 = rowj[idx];
    bool mut = (colj[b * NN + i0] == i);
    float ms0 = mut ? expf(rowv[idx]) : 0.f;
    bool valid = mut && (ms0 > TH_VAL);
    ms0_s[idx] = ms0;
    valid0[idx] = valid ? 1 : 0;
    out_m0[idx] = valid ? (float)i0 : -1.f;
    out_ms0[idx] = ms0;
}

__global__ void filter1_kernel(const int* __restrict__ rowj, const int* __restrict__ colj,
                               const float* __restrict__ ms0_s, const int* __restrict__ valid0,
                               float* __restrict__ out_m1, float* __restrict__ out_ms1)
{
    int idx = blockIdx.x * blockDim.x + threadIdx.x;
    if (idx >= 8192) return;
    int b = idx / NN, j = idx % NN;
    int i1 = colj[idx];
    bool mut = (rowj[b * MM + i1] == j);
    float ms1 = mut ? ms0_s[b * MM + i1] : 0.f;
    bool valid = mut && (valid0[b * MM + i1] != 0);
    out_m1[idx] = valid ? (float)i1 : -1.f;
    out_ms1[idx] = ms1;
}

// ---------------- host launchers ----------------
static inline void gemm_tn(const float* A, const float* A2, const float* Bt,
                           const float* bias, const float* res, const float* res2,
                           float scale, float* C,
                           int R, int N, int K, int batch, int subb,
                           long sA, long sB, long sC, long sRes)
{
    cudaFuncSetAttribute(mma_gemm<128, true, false, false, false>,
                         cudaFuncAttributeMaxDynamicSharedMemorySize, SMEM_GEMM(128));
    dim3 grid(N / 128, R / BMT, batch);
    mma_gemm<128, true, false, false, false><<<grid, 256, SMEM_GEMM(128)>>>(
        A, A2, Bt, nullptr, bias, res, res2, scale, C, N, K, subb, sA, sB, sC, sRes,
        nullptr, nullptr, nullptr, nullptr, 0, nullptr, 0, 0);
}

static inline void gemm_mp(const float* E, const float* V1, const float* V0, float* C,
                           const float* rinv, const float* cinv)
{
    cudaFuncSetAttribute(mma_gemm<128, false, false, true, false>,
                         cudaFuncAttributeMaxDynamicSharedMemorySize, SMEM_GEMM(128));
    dim3 grid(DD / 128, MM / BMT, 8);
    mma_gemm<128, false, false, true, false><<<grid, 256, SMEM_GEMM(128)>>>(
        E, E, V1, V0, nullptr, nullptr, nullptr, 1.f, C, DD, NN, 4,
        (long)MM * NN, (long)NN * DD, (long)MM * DD, 0,
        nullptr, nullptr, rinv, cinv, (long)NN, nullptr, 0, 0);
}

static inline void gemm_cat(const float* x0, const float* x1, const float* mp,
                            const float* Wcat, const float* bcat, float* C)
{
    cudaFuncSetAttribute(mma_gemm<128, true, false, false, true>,
                         cudaFuncAttributeMaxDynamicSharedMemorySize, SMEM_GEMM(128));
    dim3 grid(D2 / 128, RALLC / BMT, 2);
    mma_gemm<128, true, false, false, true><<<grid, 256, SMEM_GEMM(128)>>>(
        x0, x1, Wcat, nullptr, bcat, nullptr, nullptr, 1.f, C, D2, D2, 1,
        0, 0, (long)RALLC * D2, 0,
        nullptr, nullptr, nullptr, nullptr, 0, mp, (long)RALLC * DD, DD);
}

static inline void gemm_sim(const float* A, const float* Bt, float* C,
                            long sA, long sB, long sC, float* rp, float* cp)
{
    cudaFuncSetAttribute(mma_gemm<128, true, true, false, false>,
                         cudaFuncAttributeMaxDynamicSharedMemorySize, SMEM_GEMM(128));
    dim3 grid(NN / 128, MM / BMT, BB);
    mma_gemm<128, true, true, false, false><<<grid, 256, SMEM_GEMM(128)>>>(
        A, nullptr, Bt, nullptr, nullptr, nullptr, nullptr, 1.f, C, NN, DD, 0,
        sA, sB, sC, 0, rp, cp, nullptr, nullptr, 0, nullptr, 0, 0);
}

extern "C" void kernel_launch(void* const* d_in, const int* in_sizes, int n_in,
                              void* d_out, int out_size)
{
    const float* x0  = (const float*)d_in[0];
    const float* x1  = (const float*)d_in[1];
    const float* adj = (const float*)d_in[2];
    const float* Wv  = (const float*)d_in[3];
    const float* bv  = (const float*)d_in[4];
    const float* Wo  = (const float*)d_in[5];
    const float* bo  = (const float*)d_in[6];
    const float* Wf1 = (const float*)d_in[7];
    const float* bf1 = (const float*)d_in[8];
    const float* lng = (const float*)d_in[9];
    const float* lnb = (const float*)d_in[10];
    const float* Wf2 = (const float*)d_in[11];
    const float* bf2 = (const float*)d_in[12];
    const float* Wfp = (const float*)d_in[13];
    const float* bfp = (const float*)d_in[14];
    const float* Wz  = (const float*)d_in[15];
    const float* bz  = (const float*)d_in[16];
    float* out = (float*)d_out;

    float* S; cudaGetSymbolAddress((void**)&S, g_scratch);
    int* IS;  cudaGetSymbolAddress((void**)&IS, g_iscratch);

    float *E = S + O_E, *SIM = S + O_SIM;
    float *V0 = S + O_V0, *V1 = S + O_V1, *MP0 = S + O_MP0;
    float *H0 = S + O_H0;
    float *D0 = S + O_D0, *MD0 = S + O_MD0, *MD1 = S + O_MD1;
    float *RINV = S + O_RINV, *CINV = S + O_CINV;
    float *RLSE = S + O_RLSE, *CLSE = S + O_CLSE, *Z0 = S + O_Z0, *Z1 = S + O_Z1;
    float *RADJ = S + O_RADJ, *CADJ = S + O_CADJ, *BRD0 = S + O_BRD0, *BRD1 = S + O_BRD1;
    float *ROWV = S + O_ROWV, *MS0S = S + O_MS0;
    float *PM = S + O_PM, *PAV = S + O_PAV;
    float *WCAT = S + O_WCAT, *BCAT = S + O_BCAT, *RP = S + O_RP, *CP = S + O_CP;
    int *ROWJ = IS, *COLJ = IS + 8192, *VAL0 = IS + 16384, *PAI = IS + 24576;

    const int RALL = BB * MM;   // 8192

    // 0. weight folding (Wo into Wf1)
    fold_kernel<<<512, 256>>>(Wf1, Wo, WCAT);
    bfold_kernel<<<64, 256>>>(Wf1, bo, bf1, BCAT);

    // 1. v = x @ Wv^T + bv   (both sides, batch=2)
    gemm_tn(x0, x1, Wv, bv, nullptr, nullptr, 1.f, V0,
            RALL, DD, DD, 2, 1, 0, 0, SZV, 0);

    // 2. adjacency softmax stats: E = exp(adj), row/col sums (no-max safe)
    expstat_kernel<<<dim3(MM, BB), 256>>>(adj, E, RINV);
    colsum1_kernel<<<dim3(8, 8, BB), 256>>>(E, PM);
    colsum2_kernel<<<32, 256>>>(PM, CINV);

    // 3. message passing fused: b0-3 rinv.(E@V1); b4-7 cinv.(E^T@V0)
    gemm_mp(E, V1, V0, MP0, RINV, CINV);

    // 4. FFN with folded Wo and fused concat
    gemm_cat(x0, x1, MP0, WCAT, BCAT, H0);
    ln_gelu_kernel<<<2 * RALL, 128>>>(H0, lng, lnb);
    gemm_tn(H0, nullptr, Wf2, bf2, x0, x1, 1.f, D0,
            RALL, DD, D2, 2, 1, (long)RALL * D2, 0, SZV, 0);

    // 5. projections + z
    gemm_tn(D0, nullptr, Wfp, bfp, nullptr, nullptr, 0.25f, MD0,
            2 * RALL, DD, DD, 1, 0, 0, 0, 0, 0);
    zdot_kernel<<<(2 * RALL * 32 + 127) / 128, 128>>>(D0, Wz, bz, Z0, 2 * RALL);

    // 6. sim = md0 @ md1^T with fused row/col sum-of-exp partials
    gemm_sim(MD0, MD1, SIM, (long)MM * DD, (long)NN * DD, (long)MM * NN, RP, CP);
    merge_lse_kernel<<<64, 256>>>(RP, CP, RLSE, CLSE);

    // 7. adjustments + borders
    prep_kernel<<<32, 256>>>(Z0, Z1, RLSE, CLSE, RADJ, CADJ, BRD0, BRD1);

    // 8. scores -> d_out (+ fused row argmax)
    assemble_kernel<<<dim3(2049, BB), 256>>>(SIM, RADJ, CADJ, BRD0, BRD1, out, ROWV, ROWJ);

    // 9. col argmax (two-stage)
    colamax1_kernel<<<dim3(NN / 32, 8, BB), 256>>>(SIM, RADJ, PAV, PAI);
    colamax2_kernel<<<32, 256>>>(PAV, PAI, COLJ);

    // 10. mutual filter -> tail of d_out
    size_t OB = 4LL * 2049 * 2049;
    filter0_kernel<<<32, 256>>>(ROWJ, COLJ, ROWV, MS0S, VAL0,
                                out + OB, out + OB + 2 * 8192);
    filter1_kernel<<<32, 256>>>(ROWJ, COLJ, MS0S, VAL0,
                                out + OB + 8192, out + OB + 3 * 8192);
}

// round 16
// speedup vs baseline: 1.0058x; 1.0058x over previous
#include <cuda_runtime.h>
#include <math.h>
#include <stdint.h>

// Problem dims
#define BB 4
#define MM 2048
#define NN 2048
#define DD 256
#define D2 512
#define RALLC 8192
#define LN_EPS 1e-5f
#define TH_VAL 0.1f
#define NEG_HUGE -3.0e38f

// ---------------- scratch ----------------
#define SZP (4LL*2048*2048)
#define SZV (4LL*2048*256)
#define SZH (4LL*2048*512)
#define SZS (8192LL)
#define SZPART (65536LL)
#define STATN (4*16*2048)

constexpr size_t O_E   = 0;
constexpr size_t O_SIM = O_E + SZP;
constexpr size_t O_V0  = O_SIM + SZP;
constexpr size_t O_V1  = O_V0 + SZV;
constexpr size_t O_MP0 = O_V1 + SZV;
constexpr size_t O_MP1 = O_MP0 + SZV;
constexpr size_t O_H0  = O_MP1 + SZV;
constexpr size_t O_H1  = O_H0 + SZH;
constexpr size_t O_D0  = O_H1 + SZH;
constexpr size_t O_D1  = O_D0 + SZV;
constexpr size_t O_MD0 = O_D1 + SZV;
constexpr size_t O_MD1 = O_MD0 + SZV;
constexpr size_t O_RINV = O_MD1 + SZV;
constexpr size_t O_CINV = O_RINV + SZS;
constexpr size_t O_RLSE = O_CINV + SZS;
constexpr size_t O_CLSE = O_RLSE + SZS;
constexpr size_t O_Z0   = O_CLSE + SZS;
constexpr size_t O_Z1   = O_Z0 + SZS;
constexpr size_t O_RADJ = O_Z1 + SZS;
constexpr size_t O_CADJ = O_RADJ + SZS;
constexpr size_t O_BRD0 = O_CADJ + SZS;
constexpr size_t O_BRD1 = O_BRD0 + SZS;
constexpr size_t O_ROWV = O_BRD1 + SZS;
constexpr size_t O_MS0  = O_ROWV + SZS;
constexpr size_t O_PM   = O_MS0 + SZS;
constexpr size_t O_PAV  = O_PM + SZPART;
constexpr size_t O_WCAT = O_PAV + SZPART;
constexpr size_t O_BCAT = O_WCAT + 262144;
constexpr size_t O_RP   = O_BCAT + 512;
constexpr size_t O_CP   = O_RP + STATN;
constexpr size_t O_TOTAL = O_CP + STATN;

__device__ __align__(16) float g_scratch[O_TOTAL];
__device__ int g_iscratch[3 * 8192 + 65536];

__device__ __forceinline__ float softplusf(float x) {
    return fmaxf(x, 0.f) + log1pf(__expf(-fabsf(x)));
}

// ================= tf32x3 MMA GEMM (mask-split), double-buffered =================
__device__ __forceinline__ float lo_part(float x) {
    float h = __uint_as_float(__float_as_uint(x) & 0xFFFFE000u);
    return x - h;
}

__device__ __forceinline__ void mma8(float* c, const uint32_t* a, const uint32_t* b) {
    asm volatile(
        "mma.sync.aligned.m16n8k8.row.col.f32.tf32.tf32.f32 "
        "{%0,%1,%2,%3}, {%4,%5,%6,%7}, {%8,%9}, {%0,%1,%2,%3};\n"
        : "+f"(c[0]), "+f"(c[1]), "+f"(c[2]), "+f"(c[3])
        : "r"(a[0]), "r"(a[1]), "r"(a[2]), "r"(a[3]), "r"(b[0]), "r"(b[1]));
}

#define BMT 128
#define ASTR (BMT + 4)

template <int BN, bool B_IS_NK, bool STATS, bool TRANSA, bool SPLITA>
__global__ __launch_bounds__(256, 2) void mma_gemm(
    const float* __restrict__ A, const float* __restrict__ A2,
    const float* __restrict__ Bg, const float* __restrict__ Bg2,
    const float* __restrict__ bias,
    const float* __restrict__ res, const float* __restrict__ res2,
    float scale, float* __restrict__ C,
    int N, int K, int subbatch,
    long sA, long sB, long sC, long sRes,
    float* __restrict__ rp, float* __restrict__ cp,
    const float* __restrict__ rs, const float* __restrict__ rs2,
    long ldat,
    const float* __restrict__ Aalt, long sAalt, int kSplit)
{
    constexpr int WN = BN / 32;
    constexpr int WM = 8 / WN;
    constexpr int MROWS = BMT / WM;
    constexpr int MFRAG = MROWS / 16;
    constexpr int NFRAG = 4;
    constexpr int BSTR = BN + 4;
    constexpr int BQ = (BN * 16 / 4) / 256;

    extern __shared__ float2 dynsm[];
    float2* AsBuf = dynsm;
    float2* BsBuf = dynsm + 2 * 16 * ASTR;

    int b = blockIdx.z;
    int hb = (subbatch > 0 && b >= subbatch) ? 1 : 0;
    int b2 = b - hb * subbatch;
    const float* Ap = A2 ? ((hb ? A2 : A) + (long)b2 * sA) : (A + (long)b * sA);
    const float* Bp = Bg2 ? ((hb ? Bg2 : Bg) + (long)b2 * sB) : (Bg + (long)b * sB);
    const float* Rp = res ? (res2 ? ((hb ? res2 : res) + (long)b2 * sRes)
                                  : (res + (long)b * sRes)) : (const float*)0;
    const float* Aaltp = SPLITA ? (Aalt + (long)hb * sAalt) : (const float*)0;
    const float* rsp = rs ? ((hb ? rs2 : rs) + (long)b2 * 2048) : (const float*)0;
    float* Cp = C + (long)b * sC;
    bool atrans = TRANSA && hb;

    int bm = blockIdx.y * BMT;
    int bn = blockIdx.x * BN;
    int tid = threadIdx.x;
    int wid = tid >> 5, lane = tid & 31;
    int g = lane >> 2, t4 = lane & 3;
    int wn = wid % WN, wm = wid / WN;
    int m0 = wm * MROWS;

    float acc[MFRAG][NFRAG][4];
    #pragma unroll
    for (int i = 0; i < MFRAG; i++)
        #pragma unroll
        for (int j = 0; j < NFRAG; j++)
            #pragma unroll
            for (int q = 0; q < 4; q++) acc[i][j][q] = 0.f;

    float4 pa[2];
    float4 pb[BQ];

    int a_row = tid & 127;
    int a_kh = (tid >> 7) * 4;
    int at_k = tid >> 5;
    int at_m4 = (tid & 31) * 4;

#define LOAD_A(k0_) do { \
    if (atrans) { \
        _Pragma("unroll") \
        for (int q = 0; q < 2; q++) { \
            int kk = at_k + q * 8; \
            pa[q] = *(const float4*)(Ap + (long)((k0_) + kk) * ldat + bm + at_m4); \
        } \
    } else if (SPLITA) { \
        bool second = ((k0_) >= kSplit); \
        const float* base = second ? Aaltp : Ap; \
        int kloc = second ? (k0_) - kSplit : (k0_); \
        _Pragma("unroll") \
        for (int q = 0; q < 2; q++) \
            pa[q] = *(const float4*)(base + (long)(bm + a_row) * kSplit + kloc + q * 8 + a_kh); \
    } else { \
        _Pragma("unroll") \
        for (int q = 0; q < 2; q++) \
            pa[q] = *(const float4*)(Ap + (long)(bm + a_row) * K + (k0_) + q * 8 + a_kh); \
    } \
} while (0)

#define STORE_A(st_) do { \
    if (atrans) { \
        _Pragma("unroll") \
        for (int q = 0; q < 2; q++) { \
            int kk = at_k + q * 8; \
            float2* dst = &AsBuf[((st_) * 16 + kk) * ASTR + at_m4]; \
            dst[0] = make_float2(pa[q].x, lo_part(pa[q].x)); \
            dst[1] = make_float2(pa[q].y, lo_part(pa[q].y)); \
            dst[2] = make_float2(pa[q].z, lo_part(pa[q].z)); \
            dst[3] = make_float2(pa[q].w, lo_part(pa[q].w)); \
        } \
    } else { \
        _Pragma("unroll") \
        for (int q = 0; q < 2; q++) { \
            int k4 = q * 8 + a_kh; \
            AsBuf[((st_) * 16 + k4 + 0) * ASTR + a_row] = make_float2(pa[q].x, lo_part(pa[q].x)); \
            AsBuf[((st_) * 16 + k4 + 1) * ASTR + a_row] = make_float2(pa[q].y, lo_part(pa[q].y)); \
            AsBuf[((st_) * 16 + k4 + 2) * ASTR + a_row] = make_float2(pa[q].z, lo_part(pa[q].z)); \
            AsBuf[((st_) * 16 + k4 + 3) * ASTR + a_row] = make_float2(pa[q].w, lo_part(pa[q].w)); \
        } \
    } \
} while (0)

#define LOAD_B(k0_) do { \
    _Pragma("unroll") \
    for (int q = 0; q < BQ; q++) { \
        int idx = q * 256 + tid; \
        if (B_IS_NK) { \
            int row = idx % BN, k4 = (idx / BN) * 4; \
            pb[q] = *(const float4*)(Bp + (long)(bn + row) * K + (k0_) + k4); \
        } else { \
            int k = idx / (BN / 4), n4 = (idx % (BN / 4)) * 4; \
            pb[q] = *(const float4*)(Bp + (long)((k0_) + k) * N + bn + n4); \
        } \
    } \
} while (0)

#define STORE_B(st_) do { \
    _Pragma("unroll") \
    for (int q = 0; q < BQ; q++) { \
        int idx = q * 256 + tid; \
        if (B_IS_NK) { \
            int row = idx % BN, k4 = (idx / BN) * 4; \
            BsBuf[((st_) * 16 + k4 + 0) * BSTR + row] = make_float2(pb[q].x, lo_part(pb[q].x)); \
            BsBuf[((st_) * 16 + k4 + 1) * BSTR + row] = make_float2(pb[q].y, lo_part(pb[q].y)); \
            BsBuf[((st_) * 16 + k4 + 2) * BSTR + row] = make_float2(pb[q].z, lo_part(pb[q].z)); \
            BsBuf[((st_) * 16 + k4 + 3) * BSTR + row] = make_float2(pb[q].w, lo_part(pb[q].w)); \
        } else { \
            int k = idx / (BN / 4), n4 = (idx % (BN / 4)) * 4; \
            BsBuf[((st_) * 16 + k) * BSTR + n4 + 0] = make_float2(pb[q].x, lo_part(pb[q].x)); \
            BsBuf[((st_) * 16 + k) * BSTR + n4 + 1] = make_float2(pb[q].y, lo_part(pb[q].y)); \
            BsBuf[((st_) * 16 + k) * BSTR + n4 + 2] = make_float2(pb[q].z, lo_part(pb[q].z)); \
            BsBuf[((st_) * 16 + k) * BSTR + n4 + 3] = make_float2(pb[q].w, lo_part(pb[q].w)); \
        } \
    } \
} while (0)

#define COMPUTE(st_) do { \
    _Pragma("unroll") \
    for (int kk = 0; kk < 16; kk += 8) { \
        int kA = kk + t4; \
        uint32_t bh[NFRAG][2], bl[NFRAG][2]; \
        _Pragma("unroll") \
        for (int fn = 0; fn < NFRAG; fn++) { \
            int n = wn * 32 + fn * 8 + g; \
            float2 f0 = BsBuf[((st_) * 16 + kA) * BSTR + n]; \
            float2 f1 = BsBuf[((st_) * 16 + kA + 4) * BSTR + n]; \
            bh[fn][0] = __float_as_uint(f0.x); bh[fn][1] = __float_as_uint(f1.x); \
            bl[fn][0] = __float_as_uint(f0.y); bl[fn][1] = __float_as_uint(f1.y); \
        } \
        _Pragma("unroll") \
        for (int fm = 0; fm < MFRAG; fm++) { \
            int m = m0 + fm * 16 + g; \
            float2 f0 = AsBuf[((st_) * 16 + kA) * ASTR + m]; \
            float2 f1 = AsBuf[((st_) * 16 + kA) * ASTR + m + 8]; \
            float2 f2 = AsBuf[((st_) * 16 + kA + 4) * ASTR + m]; \
            float2 f3 = AsBuf[((st_) * 16 + kA + 4) * ASTR + m + 8]; \
            uint32_t ah[4] = {__float_as_uint(f0.x), __float_as_uint(f1.x), \
                              __float_as_uint(f2.x), __float_as_uint(f3.x)}; \
            uint32_t al[4] = {__float_as_uint(f0.y), __float_as_uint(f1.y), \
                              __float_as_uint(f2.y), __float_as_uint(f3.y)}; \
            _Pragma("unroll") \
            for (int fn = 0; fn < NFRAG; fn++) { \
                mma8(acc[fm][fn], ah, bh[fn]); \
                mma8(acc[fm][fn], ah, bl[fn]); \
                mma8(acc[fm][fn], al, bh[fn]); \
            } \
        } \
    } \
} while (0)

    int nt = K / 16;
    LOAD_A(0); LOAD_B(0);
    STORE_A(0); STORE_B(0);
    __syncthreads();
    for (int t = 0; t < nt; t++) {
        int st = t & 1;
        bool more = (t + 1 < nt);
        if (more) { LOAD_A((t + 1) * 16); LOAD_B((t + 1) * 16); }
        COMPUTE(st);
        if (more) { STORE_A(st ^ 1); STORE_B(st ^ 1); }
        __syncthreads();
    }

    if (STATS) {
        float* sst = (float*)dynsm;
        float eacc[MFRAG][NFRAG][4];
        #pragma unroll
        for (int fm = 0; fm < MFRAG; fm++)
            #pragma unroll
            for (int fn = 0; fn < NFRAG; fn++)
                #pragma unroll
                for (int q = 0; q < 4; q++)
                    eacc[fm][fn][q] = __expf(acc[fm][fn][q]);
        #pragma unroll
        for (int fm = 0; fm < MFRAG; fm++) {
            #pragma unroll
            for (int off = 0; off < 2; off++) {
                float s = 0.f;
                #pragma unroll
                for (int fn = 0; fn < NFRAG; fn++)
                    s += eacc[fm][fn][off * 2] + eacc[fm][fn][off * 2 + 1];
                s += __shfl_xor_sync(0xffffffffu, s, 1);
                s += __shfl_xor_sync(0xffffffffu, s, 2);
                if (t4 == 0) {
                    int lr = m0 + fm * 16 + off * 8 + g;
                    sst[wn * 128 + lr] = s;
                }
            }
        }
        #pragma unroll
        for (int fn = 0; fn < NFRAG; fn++) {
            #pragma unroll
            for (int c2 = 0; c2 < 2; c2++) {
                float s = 0.f;
                #pragma unroll
                for (int fm = 0; fm < MFRAG; fm++)
                    s += eacc[fm][fn][c2] + eacc[fm][fn][2 + c2];
                s += __shfl_xor_sync(0xffffffffu, s, 4);
                s += __shfl_xor_sync(0xffffffffu, s, 8);
                s += __shfl_xor_sync(0xffffffffu, s, 16);
                if (g == 0) {
                    int lc = wn * 32 + fn * 8 + t4 * 2 + c2;
                    sst[512 + wm * 128 + lc] = s;
                }
            }
        }
        __syncthreads();
        if (tid < 128) {
            float s = sst[tid];
            #pragma unroll
            for (int w = 1; w < WN; w++) s += sst[w * 128 + tid];
            long ro = ((long)blockIdx.z * 16 + blockIdx.x) * 2048 + bm + tid;
            rp[ro] = s;
            float sc = sst[512 + tid];
            #pragma unroll
            for (int w = 1; w < WM; w++) sc += sst[512 + w * 128 + tid];
            long co = ((long)blockIdx.z * 16 + blockIdx.y) * 2048 + bn + tid;
            cp[co] = sc;
        }
        __syncthreads();
    }

    #pragma unroll
    for (int fm = 0; fm < MFRAG; fm++) {
        int row0 = bm + m0 + fm * 16 + g;
        float r0s = rsp ? rsp[row0] : 1.f;
        float r1s = rsp ? rsp[row0 + 8] : 1.f;
        #pragma unroll
        for (int fn = 0; fn < NFRAG; fn++) {
            int col0 = bn + wn * 32 + fn * 8 + t4 * 2;
            float b0 = bias ? bias[col0] : 0.f;
            float b1 = bias ? bias[col0 + 1] : 0.f;
            float v00 = (acc[fm][fn][0] + b0) * scale * r0s;
            float v01 = (acc[fm][fn][1] + b1) * scale * r0s;
            float v10 = (acc[fm][fn][2] + b0) * scale * r1s;
            float v11 = (acc[fm][fn][3] + b1) * scale * r1s;
            if (Rp) {
                v00 += Rp[(long)row0 * N + col0];
                v01 += Rp[(long)row0 * N + col0 + 1];
                v10 += Rp[(long)(row0 + 8) * N + col0];
                v11 += Rp[(long)(row0 + 8) * N + col0 + 1];
            }
            *(float2*)&Cp[(long)row0 * N + col0] = make_float2(v00, v01);
            *(float2*)&Cp[(long)(row0 + 8) * N + col0] = make_float2(v10, v11);
        }
    }
#undef LOAD_A
#undef STORE_A
#undef LOAD_B
#undef STORE_B
#undef COMPUTE
}

constexpr int SMEM_GEMM(int BN) {
    return (2 * 16 * (BMT + 4) + 2 * 16 * (BN + 4)) * (int)sizeof(float2);
}

// ================= weight folding =================
__global__ void fold_kernel(const float* __restrict__ Wf1, const float* __restrict__ Wo,
                            float* __restrict__ Wcat)
{
    int i = blockIdx.x;
    int k = threadIdx.x;
    float a0 = 0.f, a1 = 0.f, a2 = 0.f, a3 = 0.f;
    const float* wrow = Wf1 + (size_t)i * 512 + 256;
    #pragma unroll 4
    for (int j = 0; j < 256; j += 4) {
        a0 = fmaf(wrow[j + 0], Wo[(j + 0) * 256 + k], a0);
        a1 = fmaf(wrow[j + 1], Wo[(j + 1) * 256 + k], a1);
        a2 = fmaf(wrow[j + 2], Wo[(j + 2) * 256 + k], a2);
        a3 = fmaf(wrow[j + 3], Wo[(j + 3) * 256 + k], a3);
    }
    Wcat[(size_t)i * 512 + 256 + k] = (a0 + a1) + (a2 + a3);
    Wcat[(size_t)i * 512 + k] = Wf1[(size_t)i * 512 + k];
}

__global__ void bfold_kernel(const float* __restrict__ Wf1, const float* __restrict__ bo,
                             const float* __restrict__ bf1, float* __restrict__ bcat)
{
    int warp = (blockIdx.x * blockDim.x + threadIdx.x) >> 5;
    int lane = threadIdx.x & 31;
    if (warp >= 512) return;
    float s = 0.f;
    for (int j = lane; j < 256; j += 32)
        s += Wf1[(size_t)warp * 512 + 256 + j] * bo[j];
    for (int o = 16; o; o >>= 1) s += __shfl_down_sync(0xffffffffu, s, o);
    if (lane == 0) bcat[warp] = bf1[warp] + s;
}

// ================= adj softmax: E = exp(adj), row sums =================
__global__ void expstat_kernel(const float* __restrict__ adj, float* __restrict__ E,
                               float* __restrict__ rinv)
{
    int b = blockIdx.y, row = blockIdx.x, tid = threadIdx.x;
    const float4* ar = (const float4*)(adj + ((size_t)b * MM + row) * NN);
    float4* er = (float4*)(E + ((size_t)b * MM + row) * NN);
    float s = 0.f;
    #pragma unroll
    for (int it = 0; it < 2; it++) {
        int j = tid + it * 256;
        float4 v = ar[j];
        float4 e = make_float4(__expf(v.x), __expf(v.y), __expf(v.z), __expf(v.w));
        er[j] = e;
        s += (e.x + e.y) + (e.z + e.w);
    }
    __shared__ float red[256];
    red[tid] = s; __syncthreads();
    for (int o = 128; o; o >>= 1) { if (tid < o) red[tid] += red[tid + o]; __syncthreads(); }
    if (tid == 0) rinv[b * MM + row] = 1.f / red[0];
}

__global__ void colsum1_kernel(const float* __restrict__ E, float* __restrict__ ps)
{
    int b = blockIdx.z, ch = blockIdx.y;
    int col = blockIdx.x * 256 + threadIdx.x;
    const float* Eb = E + (size_t)b * MM * NN;
    int r0 = ch * 256;
    float s0 = 0.f, s1 = 0.f, s2 = 0.f, s3 = 0.f;
    for (int i = 0; i < 256; i += 4) {
        s0 += Eb[(size_t)(r0 + i + 0) * NN + col];
        s1 += Eb[(size_t)(r0 + i + 1) * NN + col];
        s2 += Eb[(size_t)(r0 + i + 2) * NN + col];
        s3 += Eb[(size_t)(r0 + i + 3) * NN + col];
    }
    ps[((size_t)b * 8 + ch) * NN + col] = (s0 + s1) + (s2 + s3);
}

__global__ void colsum2_kernel(const float* __restrict__ ps, float* __restrict__ cinv)
{
    int idx = blockIdx.x * blockDim.x + threadIdx.x;
    if (idx >= BB * NN) return;
    int b = idx / NN, col = idx % NN;
    size_t base = (size_t)b * 8 * NN + col;
    float s = 0.f;
    #pragma unroll
    for (int ch = 0; ch < 8; ch++) s += ps[base + (size_t)ch * NN];
    cinv[idx] = 1.f / s;
}

// ================= fused: merge LSE partials + prep adjustments =================
__global__ void lse_prep_kernel(const float* __restrict__ rp, const float* __restrict__ cp,
                                const float* __restrict__ z0, const float* __restrict__ z1,
                                float* __restrict__ radj, float* __restrict__ cadj,
                                float* __restrict__ brd0, float* __restrict__ brd1)
{
    int idx = blockIdx.x * blockDim.x + threadIdx.x;
    if (idx >= 2 * 8192) return;
    bool iscol = idx >= 8192;
    int j = iscol ? idx - 8192 : idx;
    int b = j / 2048, r = j % 2048;
    const float* pm = iscol ? cp : rp;
    long base = ((long)b * 16) * 2048 + r;
    float s = 0.f;
    #pragma unroll
    for (int t = 0; t < 16; t++) s += pm[base + (long)t * 2048];
    float lse = __logf(s);
    if (iscol) {
        float zb = z1[j];
        cadj[j] = -softplusf(-zb) - lse;
        brd1[j] = -softplusf(zb);
    } else {
        float za = z0[j];
        radj[j] = -softplusf(-za) - lse;
        brd0[j] = -softplusf(za);
    }
}

// ================= col argmax =================
#define RCH 256
__global__ void colamax1_kernel(const float* __restrict__ sim, const float* __restrict__ radj,
                                float* __restrict__ pav, int* __restrict__ pai)
{
    int b = blockIdx.z, ch = blockIdx.y;
    int tid = threadIdx.x;
    int col = blockIdx.x * 32 + (tid & 31);
    int part = tid >> 5;
    const float* Sb = sim + (size_t)b * MM * NN;
    int r0 = ch * RCH;
    float bv[4]; int bx[4];
    #pragma unroll
    for (int q = 0; q < 4; q++) { bv[q] = NEG_HUGE; bx[q] = 0; }
    #pragma unroll 2
    for (int it = 0; it < 32; it += 4) {
        #pragma unroll
        for (int q = 0; q < 4; q++) {
            int i = r0 + part + (it + q) * 8;
            float v = 2.f * Sb[(size_t)i * NN + col] + radj[b * MM + i];
            if (v > bv[q]) { bv[q] = v; bx[q] = i; }
        }
    }
    float best = bv[0]; int bi = bx[0];
    #pragma unroll
    for (int q = 1; q < 4; q++)
        if (bv[q] > best || (bv[q] == best && bx[q] < bi)) { best = bv[q]; bi = bx[q]; }
    __shared__ float sv[256]; __shared__ int si[256];
    sv[tid] = best; si[tid] = bi; __syncthreads();
    if (part == 0) {
        for (int p = 1; p < 8; p++) {
            float v2 = sv[p * 32 + tid]; int i2 = si[p * 32 + tid];
            if (v2 > best || (v2 == best && i2 < bi)) { best = v2; bi = i2; }
        }
        size_t o = ((size_t)b * 8 + ch) * NN + col;
        pav[o] = best; pai[o] = bi;
    }
}

__global__ void colamax2_kernel(const float* __restrict__ pav, const int* __restrict__ pai,
                                int* __restrict__ colj)
{
    int idx = blockIdx.x * blockDim.x + threadIdx.x;
    if (idx >= BB * NN) return;
    int b = idx / NN, col = idx % NN;
    size_t base = (size_t)b * 8 * NN + col;
    float best = pav[base]; int bi = pai[base];
    for (int ch = 1; ch < 8; ch++) {
        float v2 = pav[base + (size_t)ch * NN];
        int i2 = pai[base + (size_t)ch * NN];
        if (v2 > best || (v2 == best && i2 < bi)) { best = v2; bi = i2; }
    }
    colj[idx] = bi;
}

// ---------------- layernorm + exact gelu ----------------
__global__ void ln_gelu_kernel(float* __restrict__ H, const float* __restrict__ g,
                               const float* __restrict__ bb)
{
    int row = blockIdx.x, tid = threadIdx.x;
    float* h = H + (size_t)row * 512;
    float x[4];
    float s = 0.f;
    __shared__ float red[128];
    #pragma unroll
    for (int i = 0; i < 4; i++) { x[i] = h[tid + i * 128]; s += x[i]; }
    red[tid] = s; __syncthreads();
    for (int o = 64; o; o >>= 1) { if (tid < o) red[tid] += red[tid + o]; __syncthreads(); }
    float mu = red[0] * (1.f / 512.f); __syncthreads();
    float s2 = 0.f;
    #pragma unroll
    for (int i = 0; i < 4; i++) { float d = x[i] - mu; s2 += d * d; }
    red[tid] = s2; __syncthreads();
    for (int o = 64; o; o >>= 1) { if (tid < o) red[tid] += red[tid + o]; __syncthreads(); }
    float rstd = rsqrtf(red[0] * (1.f / 512.f) + LN_EPS);
    #pragma unroll
    for (int i = 0; i < 4; i++) {
        int c = tid + i * 128;
        float y = (x[i] - mu) * rstd * g[c] + bb[c];
        h[c] = y * 0.5f * (1.f + erff(y * 0.70710678118654752f));
    }
}

// ---------------- z = d @ Wz + bz ----------------
__global__ void zdot_kernel(const float* __restrict__ Dm, const float* __restrict__ Wz,
                            const float* __restrict__ bz, float* __restrict__ z, int rows)
{
    int warp = (blockIdx.x * blockDim.x + threadIdx.x) >> 5;
    int lane = threadIdx.x & 31;
    if (warp >= rows) return;
    const float* r = Dm + (size_t)warp * DD;
    float s = 0.f;
    for (int k = lane; k < DD; k += 32) s += r[k] * Wz[k];
    for (int o = 16; o; o >>= 1) s += __shfl_down_sync(0xffffffffu, s, o);
    if (lane == 0) z[warp] = s + bz[0];
}

// ---------------- scores assembly + fused row argmax ----------------
__global__ void assemble_kernel(const float* __restrict__ sim,
                                const float* __restrict__ radj, const float* __restrict__ cadj,
                                const float* __restrict__ brd0, const float* __restrict__ brd1,
                                float* __restrict__ out,
                                float* __restrict__ rowv, int* __restrict__ rowj)
{
    int b = blockIdx.y, i = blockIdx.x, tid = threadIdx.x;
    float* o = out + (size_t)b * 2049 * 2049 + (size_t)i * 2049;
    if (i < MM) {
        const float* sr = sim + (size_t)b * MM * NN + (size_t)i * NN;
        float ra = radj[b * MM + i];
        float best = NEG_HUGE; int bj = 0;
        for (int j = tid; j < NN; j += 256) {
            float v = 2.f * sr[j] + cadj[b * NN + j];
            o[j] = v + ra;
            if (v > best) { best = v; bj = j; }
        }
        __shared__ float sv[256]; __shared__ int sj[256];
        sv[tid] = best; sj[tid] = bj; __syncthreads();
        for (int off = 128; off; off >>= 1) {
            if (tid < off) {
                float v2 = sv[tid + off]; int j2 = sj[tid + off];
                if (v2 > sv[tid] || (v2 == sv[tid] && j2 < sj[tid])) { sv[tid] = v2; sj[tid] = j2; }
            }
            __syncthreads();
        }
        if (tid == 0) {
            o[NN] = brd0[b * MM + i];
            rowv[b * MM + i] = sv[0] + ra;
            rowj[b * MM + i] = sj[0];
        }
    } else {
        for (int j = tid; j < NN; j += 256)
            o[j] = brd1[b * NN + j];
        if (tid == 0) o[NN] = 0.f;
    }
}

// ---------------- mutual-match filter ----------------
__global__ void filter0_kernel(const int* __restrict__ rowj, const int* __restrict__ colj,
                               const float* __restrict__ rowv,
                               float* __restrict__ ms0_s, int* __restrict__ valid0,
                               float* __restrict__ out_m0, float* __restrict__ out_ms0)
{
    int idx = blockIdx.x * blockDim.x + threadIdx.x;
    if (idx >= 8192) return;
    int b = idx / MM, i = idx % MM;
    int i0 = rowj[idx];
    bool mut = (colj[b * NN + i0] == i);
    float ms0 = mut ? __expf(rowv[idx]) : 0.f;
    bool valid = mut && (ms0 > TH_VAL);
    ms0_s[idx] = ms0;
    valid0[idx] = valid ? 1 : 0;
    out_m0[idx] = valid ? (float)i0 : -1.f;
    out_ms0[idx] = ms0;
}

__global__ void filter1_kernel(const int* __restrict__ rowj, const int* __restrict__ colj,
                               const float* __restrict__ ms0_s, const int* __restrict__ valid0,
                               float* __restrict__ out_m1, float* __restrict__ out_ms1)
{
    int idx = blockIdx.x * blockDim.x + threadIdx.x;
    if (idx >= 8192) return;
    int b = idx / NN, j = idx % NN;
    int i1 = colj[idx];
    bool mut = (rowj[b * MM + i1] == j);
    float ms1 = mut ? ms0_s[b * MM + i1] : 0.f;
    bool valid = mut && (valid0[b * MM + i1] != 0);
    out_m1[idx] = valid ? (float)i1 : -1.f;
    out_ms1[idx] = ms1;
}

// ---------------- host launchers ----------------
static inline void gemm_tn(const float* A, const float* A2, const float* Bt,
                           const float* bias, const float* res, const float* res2,
                           float scale, float* C,
                           int R, int N, int K, int batch, int subb,
                           long sA, long sB, long sC, long sRes)
{
    cudaFuncSetAttribute(mma_gemm<128, true, false, false, false>,
                         cudaFuncAttributeMaxDynamicSharedMemorySize, SMEM_GEMM(128));
    dim3 grid(N / 128, R / BMT, batch);
    mma_gemm<128, true, false, false, false><<<grid, 256, SMEM_GEMM(128)>>>(
        A, A2, Bt, nullptr, bias, res, res2, scale, C, N, K, subb, sA, sB, sC, sRes,
        nullptr, nullptr, nullptr, nullptr, 0, nullptr, 0, 0);
}

static inline void gemm_mp(const float* E, const float* V1, const float* V0, float* C,
                           const float* rinv, const float* cinv)
{
    cudaFuncSetAttribute(mma_gemm<128, false, false, true, false>,
                         cudaFuncAttributeMaxDynamicSharedMemorySize, SMEM_GEMM(128));
    dim3 grid(DD / 128, MM / BMT, 8);
    mma_gemm<128, false, false, true, false><<<grid, 256, SMEM_GEMM(128)>>>(
        E, E, V1, V0, nullptr, nullptr, nullptr, 1.f, C, DD, NN, 4,
        (long)MM * NN, (long)NN * DD, (long)MM * DD, 0,
        nullptr, nullptr, rinv, cinv, (long)NN, nullptr, 0, 0);
}

static inline void gemm_cat(const float* x0, const float* x1, const float* mp,
                            const float* Wcat, const float* bcat, float* C)
{
    cudaFuncSetAttribute(mma_gemm<128, true, false, false, true>,
                         cudaFuncAttributeMaxDynamicSharedMemorySize, SMEM_GEMM(128));
    dim3 grid(D2 / 128, RALLC / BMT, 2);
    mma_gemm<128, true, false, false, true><<<grid, 256, SMEM_GEMM(128)>>>(
        x0, x1, Wcat, nullptr, bcat, nullptr, nullptr, 1.f, C, D2, D2, 1,
        0, 0, (long)RALLC * D2, 0,
        nullptr, nullptr, nullptr, nullptr, 0, mp, (long)RALLC * DD, DD);
}

static inline void gemm_sim(const float* A, const float* Bt, float* C,
                            long sA, long sB, long sC, float* rp, float* cp)
{
    cudaFuncSetAttribute(mma_gemm<128, true, true, false, false>,
                         cudaFuncAttributeMaxDynamicSharedMemorySize, SMEM_GEMM(128));
    dim3 grid(NN / 128, MM / BMT, BB);
    mma_gemm<128, true, true, false, false><<<grid, 256, SMEM_GEMM(128)>>>(
        A, nullptr, Bt, nullptr, nullptr, nullptr, nullptr, 1.f, C, NN, DD, 0,
        sA, sB, sC, 0, rp, cp, nullptr, nullptr, 0, nullptr, 0, 0);
}

extern "C" void kernel_launch(void* const* d_in, const int* in_sizes, int n_in,
                              void* d_out, int out_size)
{
    const float* x0  = (const float*)d_in[0];
    const float* x1  = (const float*)d_in[1];
    const float* adj = (const float*)d_in[2];
    const float* Wv  = (const float*)d_in[3];
    const float* bv  = (const float*)d_in[4];
    const float* Wo  = (const float*)d_in[5];
    const float* bo  = (const float*)d_in[6];
    const float* Wf1 = (const float*)d_in[7];
    const float* bf1 = (const float*)d_in[8];
    const float* lng = (const float*)d_in[9];
    const float* lnb = (const float*)d_in[10];
    const float* Wf2 = (const float*)d_in[11];
    const float* bf2 = (const float*)d_in[12];
    const float* Wfp = (const float*)d_in[13];
    const float* bfp = (const float*)d_in[14];
    const float* Wz  = (const float*)d_in[15];
    const float* bz  = (const float*)d_in[16];
    float* out = (float*)d_out;

    float* S; cudaGetSymbolAddress((void**)&S, g_scratch);
    int* IS;  cudaGetSymbolAddress((void**)&IS, g_iscratch);

    float *E = S + O_E, *SIM = S + O_SIM;
    float *V0 = S + O_V0, *V1 = S + O_V1, *MP0 = S + O_MP0;
    float *H0 = S + O_H0;
    float *D0 = S + O_D0, *MD0 = S + O_MD0, *MD1 = S + O_MD1;
    float *RINV = S + O_RINV, *CINV = S + O_CINV;
    float *Z0 = S + O_Z0, *Z1 = S + O_Z1;
    float *RADJ = S + O_RADJ, *CADJ = S + O_CADJ, *BRD0 = S + O_BRD0, *BRD1 = S + O_BRD1;
    float *ROWV = S + O_ROWV, *MS0S = S + O_MS0;
    float *PM = S + O_PM, *PAV = S + O_PAV;
    float *WCAT = S + O_WCAT, *BCAT = S + O_BCAT, *RP = S + O_RP, *CP = S + O_CP;
    int *ROWJ = IS, *COLJ = IS + 8192, *VAL0 = IS + 16384, *PAI = IS + 24576;

    const int RALL = BB * MM;   // 8192

    // 0. weight folding (Wo into Wf1)
    fold_kernel<<<512, 256>>>(Wf1, Wo, WCAT);
    bfold_kernel<<<64, 256>>>(Wf1, bo, bf1, BCAT);

    // 1. v = x @ Wv^T + bv   (both sides, batch=2)
    gemm_tn(x0, x1, Wv, bv, nullptr, nullptr, 1.f, V0,
            RALL, DD, DD, 2, 1, 0, 0, SZV, 0);

    // 2. adjacency softmax stats: E = exp(adj), row/col sums (no-max safe)
    expstat_kernel<<<dim3(MM, BB), 256>>>(adj, E, RINV);
    colsum1_kernel<<<dim3(8, 8, BB), 256>>>(E, PM);
    colsum2_kernel<<<32, 256>>>(PM, CINV);

    // 3. message passing fused: b0-3 rinv.(E@V1); b4-7 cinv.(E^T@V0)
    gemm_mp(E, V1, V0, MP0, RINV, CINV);

    // 4. FFN with folded Wo and fused concat
    gemm_cat(x0, x1, MP0, WCAT, BCAT, H0);
    ln_gelu_kernel<<<2 * RALL, 128>>>(H0, lng, lnb);
    gemm_tn(H0, nullptr, Wf2, bf2, x0, x1, 1.f, D0,
            RALL, DD, D2, 2, 1, (long)RALL * D2, 0, SZV, 0);

    // 5. projections + z
    gemm_tn(D0, nullptr, Wfp, bfp, nullptr, nullptr, 0.25f, MD0,
            2 * RALL, DD, DD, 1, 0, 0, 0, 0, 0);
    zdot_kernel<<<(2 * RALL * 32 + 127) / 128, 128>>>(D0, Wz, bz, Z0, 2 * RALL);

    // 6. sim = md0 @ md1^T with fused row/col sum-of-exp partials
    gemm_sim(MD0, MD1, SIM, (long)MM * DD, (long)NN * DD, (long)MM * NN, RP, CP);

    // 7. fused LSE merge + adjustments + borders
    lse_prep_kernel<<<64, 256>>>(RP, CP, Z0, Z1, RADJ, CADJ, BRD0, BRD1);

    // 8. scores -> d_out (+ fused row argmax)
    assemble_kernel<<<dim3(2049, BB), 256>>>(SIM, RADJ, CADJ, BRD0, BRD1, out, ROWV, ROWJ);

    // 9. col argmax (two-stage)
    colamax1_kernel<<<dim3(NN / 32, 8, BB), 256>>>(SIM, RADJ, PAV, PAI);
    colamax2_kernel<<<32, 256>>>(PAV, PAI, COLJ);

    // 10. mutual filter -> tail of d_out
    size_t OB = 4LL * 2049 * 2049;
    filter0_kernel<<<32, 256>>>(ROWJ, COLJ, ROWV, MS0S, VAL0,
                                out + OB, out + OB + 2 * 8192);
    filter1_kernel<<<32, 256>>>(ROWJ, COLJ, MS0S, VAL0,
                                out + OB + 8192, out + OB + 3 * 8192);
}